// round 1
// baseline (speedup 1.0000x reference)
#include <cuda_runtime.h>
#include <cuda_bf16.h>

// Problem constants
#define Bz 16
#define Nn 5000
#define Ff 64
#define Hh 32
#define Ee 160000
#define Aa 16
#define NE (Ee + Nn)          // 165000 edges incl self loops
#define NH (Nn * Hh)          // 160000 = K of policy GEMM
#define Jj 512                // policy hidden
#define SPLITS 296
#define KLEN 541              // ceil(160000/296)

// ----------------------------- scratch (no allocs allowed) ------------------
__device__ int   g_is64;
__device__ int   g_deg[Nn];
__device__ int   g_ptr[Nn + 1];
__device__ int   g_cursor[Nn];
__device__ float g_dinv[Nn];
__device__ int   g_csr_src[NE];                 // stores src*32 (pre-scaled offset)
__device__ __align__(16) float g_y1[Bz * NH];   // dinv * X@W1   [b][n][h]
__device__ __align__(16) float g_y2[Bz * NH];   // dinv * h1@W2  [b][n][h]
__device__ __align__(16) float g_flatT[NH * Bz];// layer2 out    [k=n*32+h][b]
__device__ __align__(16) float g_partial[SPLITS * Jj * Bz];
__device__ __align__(16) float g_hid[Jj * Bz];  // relu(flat@Wp1+bp1) [j][b]

// ----------------------------- helpers --------------------------------------
__device__ __forceinline__ unsigned long long ffma2(unsigned long long a,
                                                    unsigned long long b,
                                                    unsigned long long c) {
    unsigned long long d;
    asm("fma.rn.f32x2 %0, %1, %2, %3;" : "=l"(d) : "l"(a), "l"(b), "l"(c));
    return d;
}
__device__ __forceinline__ unsigned long long pack2(float x) {
    unsigned long long d;
    unsigned u = __float_as_uint(x);
    asm("mov.b64 %0, {%1, %1};" : "=l"(d) : "r"(u));
    return d;
}
__device__ __forceinline__ int load_idx(const void* ei, long long pos) {
    if (g_is64) return (int)((const long long*)ei)[pos];
    return ((const int*)ei)[pos];
}

// ------------------- 1. init: zero deg + detect int32/int64 -----------------
__global__ void k_init(const void* ei) {
    int tid = threadIdx.x;
    for (int i = tid; i < Nn; i += 256) g_deg[i] = 0;
    const unsigned* w = (const unsigned*)ei;
    unsigned o = 0;
    for (int i = tid; i < 2048; i += 256) o |= w[2 * i + 1]; // high words if i64
    __shared__ unsigned red[256];
    red[tid] = o;
    __syncthreads();
    for (int s = 128; s > 0; s >>= 1) {
        if (tid < s) red[tid] |= red[tid + s];
        __syncthreads();
    }
    if (tid == 0) g_is64 = (red[0] == 0u) ? 1 : 0;
}

// ------------------- 2. degree histogram ------------------------------------
__global__ void k_degree(const void* ei) {
    int idx = blockIdx.x * 256 + threadIdx.x;
    if (idx >= NE) return;
    int d = (idx < Ee) ? load_idx(ei, (long long)Ee + idx) : (idx - Ee);
    atomicAdd(&g_deg[d], 1);
}

// ------------------- 3. scan: ptr, cursor, dinv ------------------------------
__global__ void k_scan() {
    __shared__ int ss[1024];
    __shared__ int sCarry;
    int tid = threadIdx.x;
    if (tid == 0) sCarry = 0;
    __syncthreads();
    for (int c0 = 0; c0 < Nn; c0 += 1024) {
        int i = c0 + tid;
        int v = (i < Nn) ? g_deg[i] : 0;
        if (i < Nn) g_dinv[i] = rsqrtf((float)v);   // deg >= 1 (self loop)
        ss[tid] = v;
        __syncthreads();
        for (int off = 1; off < 1024; off <<= 1) {
            int t = (tid >= off) ? ss[tid - off] : 0;
            __syncthreads();
            ss[tid] += t;
            __syncthreads();
        }
        int excl = sCarry + ss[tid] - v;
        if (i < Nn) { g_ptr[i] = excl; g_cursor[i] = excl; }
        int tot = ss[1023];
        __syncthreads();
        if (tid == 0) sCarry += tot;
        __syncthreads();
    }
    if (tid == 0) g_ptr[Nn] = NE;
}

// ------------------- 4. bucket edges by dst ---------------------------------
__global__ void k_bucket(const void* ei) {
    int idx = blockIdx.x * 256 + threadIdx.x;
    if (idx >= NE) return;
    int d, s;
    if (idx < Ee) {
        d = load_idx(ei, (long long)Ee + idx);
        s = load_idx(ei, idx);
    } else {
        d = s = idx - Ee;
    }
    int pos = atomicAdd(&g_cursor[d], 1);
    g_csr_src[pos] = s * Hh;   // pre-scale: offset within [b] slab
}

// ------------------- 5. y1 = dinv * (X @ W1)  -------------------------------
__global__ void __launch_bounds__(256) k_xw1(const float* __restrict__ X,
                                             const float* __restrict__ W1) {
    __shared__ float sW[Ff * Hh];      // 8KB
    __shared__ float sX[Ff * 33];      // [f][row] padded
    int tid = threadIdx.x;
    int rbase = blockIdx.x * 32;       // 2500 blocks x 32 rows
    for (int i = tid; i < Ff * Hh; i += 256) sW[i] = W1[i];
    for (int i = tid; i < 32 * Ff; i += 256) {
        int row = i >> 6, f = i & 63;
        sX[f * 33 + row] = X[(size_t)(rbase + row) * Ff + f];
    }
    __syncthreads();
    int row = tid >> 3;
    int h0 = (tid & 7) * 4;
    int r = rbase + row;               // r = b*5000 + n
    float a0 = 0.f, a1 = 0.f, a2 = 0.f, a3 = 0.f;
#pragma unroll
    for (int f = 0; f < Ff; f++) {
        float x = sX[f * 33 + row];
        float4 w = *(const float4*)&sW[f * Hh + h0];
        a0 += x * w.x; a1 += x * w.y; a2 += x * w.z; a3 += x * w.w;
    }
    float di = g_dinv[r % Nn];
    float4 o = make_float4(di * a0, di * a1, di * a2, di * a3);
    *(float4*)&g_y1[(size_t)r * Hh + h0] = o;
}

// ------------------- 6. layer1 aggregate + relu + @W2 fused ------------------
__global__ void __launch_bounds__(512) k_agg1(const float* __restrict__ W2,
                                              const float* __restrict__ b1) {
    __shared__ float sW2[Hh * Hh];     // 4KB
    __shared__ int   sE[512];
    __shared__ float sH[512];
    int d = blockIdx.x;
    int tid = threadIdx.x;
    int b = tid >> 5, h = tid & 31;
    sW2[tid] = W2[tid];
    sW2[tid + 512] = W2[tid + 512];
    int start = g_ptr[d], end = g_ptr[d + 1];
    const float* yb = g_y1 + (size_t)b * NH + h;
    float acc = 0.f, acc2 = 0.f;
    for (int base = start; base < end; base += 512) {
        int cnt = min(end - base, 512);
        __syncthreads();
        if (tid < cnt) sE[tid] = g_csr_src[base + tid];
        __syncthreads();
        int i = 0;
#pragma unroll 2
        for (; i + 1 < cnt; i += 2) {
            acc  += __ldg(yb + sE[i]);
            acc2 += __ldg(yb + sE[i + 1]);
        }
        if (i < cnt) acc += __ldg(yb + sE[i]);
    }
    float di = g_dinv[d];
    float hv = fmaxf(di * (acc + acc2) + b1[h], 0.f);
    __syncthreads();
    sH[tid] = hv;                      // [b][h']
    __syncthreads();
    float a = 0.f;
    const float* hb = sH + b * Hh;
#pragma unroll
    for (int hp = 0; hp < Hh; hp++) a += hb[hp] * sW2[hp * Hh + h];
    g_y2[(size_t)b * NH + (size_t)d * Hh + h] = di * a;
}

// ------------------- 7. layer2 aggregate + relu -> flatT ---------------------
__global__ void __launch_bounds__(512) k_agg2(const float* __restrict__ b2) {
    __shared__ int   sE[512];
    __shared__ float sT[32 * 17];
    int d = blockIdx.x;
    int tid = threadIdx.x;
    int b = tid >> 5, h = tid & 31;
    int start = g_ptr[d], end = g_ptr[d + 1];
    const float* yb = g_y2 + (size_t)b * NH + h;
    float acc = 0.f, acc2 = 0.f;
    for (int base = start; base < end; base += 512) {
        int cnt = min(end - base, 512);
        __syncthreads();
        if (tid < cnt) sE[tid] = g_csr_src[base + tid];
        __syncthreads();
        int i = 0;
#pragma unroll 2
        for (; i + 1 < cnt; i += 2) {
            acc  += __ldg(yb + sE[i]);
            acc2 += __ldg(yb + sE[i + 1]);
        }
        if (i < cnt) acc += __ldg(yb + sE[i]);
    }
    float di = g_dinv[d];
    float v = fmaxf(di * (acc + acc2) + b2[h], 0.f);
    sT[h * 17 + b] = v;
    __syncthreads();
    int hh = tid >> 4, bb = tid & 15;
    g_flatT[(size_t)d * 512 + tid] = sT[hh * 17 + bb];
}

// ------------------- 8. big GEMM: partial[split] = flatT^T chunk @ Wp1 -------
__global__ void __launch_bounds__(256) k_gemm1(const float* __restrict__ Wp1) {
    int t = threadIdx.x, sp = blockIdx.x;
    int ks = sp * KLEN;
    int ke = min(ks + KLEN, NH);
    unsigned long long acc0[8], acc1[8];
#pragma unroll
    for (int p = 0; p < 8; p++) { acc0[p] = 0ull; acc1[p] = 0ull; }
    const float2* wp = (const float2*)Wp1;             // [k][256 pairs]
    const ulonglong2* fp = (const ulonglong2*)g_flatT; // 16B = 2 batch-pairs
#pragma unroll 4
    for (int k = ks; k < ke; k++) {
        float2 w = __ldg(&wp[(size_t)k * 256 + t]);
        unsigned long long wa = pack2(w.x), wb = pack2(w.y);
        ulonglong2 f0 = fp[(size_t)k * 4 + 0];
        ulonglong2 f1 = fp[(size_t)k * 4 + 1];
        ulonglong2 f2 = fp[(size_t)k * 4 + 2];
        ulonglong2 f3 = fp[(size_t)k * 4 + 3];
        unsigned long long fv[8] = {f0.x, f0.y, f1.x, f1.y, f2.x, f2.y, f3.x, f3.y};
#pragma unroll
        for (int p = 0; p < 8; p++) {
            acc0[p] = ffma2(fv[p], wa, acc0[p]);
            acc1[p] = ffma2(fv[p], wb, acc1[p]);
        }
    }
    int j0 = 2 * t;
    unsigned long long* po = (unsigned long long*)g_partial;
    size_t base = (size_t)sp * 4096 + (size_t)j0 * 8;
#pragma unroll
    for (int p = 0; p < 8; p++) {
        po[base + p] = acc0[p];
        po[base + 8 + p] = acc1[p];
    }
}

// ------------------- 9. reduce partials + bias + relu ------------------------
__global__ void __launch_bounds__(256) k_reduce(const float* __restrict__ bp1) {
    int idx = blockIdx.x * 256 + threadIdx.x;   // [j][b], 8192 total
    float s = 0.f;
#pragma unroll 4
    for (int sp = 0; sp < SPLITS; sp++) s += g_partial[(size_t)sp * 8192 + idx];
    g_hid[idx] = fmaxf(s + bp1[idx >> 4], 0.f);
}

// ------------------- 10. final tiny GEMM ------------------------------------
__global__ void __launch_bounds__(256) k_out(const float* __restrict__ Wp2,
                                             const float* __restrict__ bp2,
                                             float* __restrict__ out) {
    int tid = threadIdx.x;
    int b = tid >> 4, a = tid & 15;
    float acc = 0.f;
#pragma unroll 4
    for (int j = 0; j < Jj; j++)
        acc += __ldg(&g_hid[j * 16 + b]) * __ldg(&Wp2[j * 16 + a]);
    out[tid] = acc + bp2[a];
}

// ----------------------------- launcher -------------------------------------
extern "C" void kernel_launch(void* const* d_in, const int* in_sizes, int n_in,
                              void* d_out, int out_size) {
    const float* features = (const float*)d_in[0];
    const void*  edge_ix  = d_in[1];
    const float* W1  = (const float*)d_in[2];
    const float* b1  = (const float*)d_in[3];
    const float* W2  = (const float*)d_in[4];
    const float* b2  = (const float*)d_in[5];
    const float* Wp1 = (const float*)d_in[6];
    const float* bp1 = (const float*)d_in[7];
    const float* Wp2 = (const float*)d_in[8];
    const float* bp2 = (const float*)d_in[9];
    float* out = (float*)d_out;

    k_init<<<1, 256>>>(edge_ix);
    k_degree<<<(NE + 255) / 256, 256>>>(edge_ix);
    k_scan<<<1, 1024>>>();
    k_bucket<<<(NE + 255) / 256, 256>>>(edge_ix);
    k_xw1<<<(Bz * Nn) / 32, 256>>>(features, W1);
    k_agg1<<<Nn, 512>>>(W2, b1);
    k_agg2<<<Nn, 512>>>(b2);
    k_gemm1<<<SPLITS, 256>>>(Wp1);
    k_reduce<<<Jj * Bz / 256, 256>>>(bp1);
    k_out<<<1, 256>>>(Wp2, bp2, out);
}

// round 2
// speedup vs baseline: 1.7125x; 1.7125x over previous
#include <cuda_runtime.h>
#include <cuda_bf16.h>

// Problem constants
#define Bz 16
#define Nn 5000
#define Ff 64
#define Hh 32
#define Ee 160000
#define Aa 16
#define NE (Ee + Nn)          // 165000 edges incl self loops
#define NH (Nn * Hh)          // 160000 = K of policy GEMM
#define Jj 512                // policy hidden
#define SPLITS 296
#define KLEN 544              // 296*544 = 161024 >= 160000, multiple of 8

// ----------------------------- scratch (no allocs allowed) ------------------
__device__ int   g_is64;
__device__ int   g_deg[Nn];
__device__ int   g_ptr[Nn + 1];
__device__ int   g_cursor[Nn];
__device__ float g_dinv[Nn];
__device__ int   g_csr_src[NE];                 // stores src*32 (pre-scaled offset)
__device__ __align__(16) float g_y1[Bz * NH];   // dinv * X@W1   [b][n][h]
__device__ __align__(16) float g_y2[Bz * NH];   // dinv * h1@W2  [b][n][h]
__device__ __align__(16) float g_flatT[NH * Bz];// layer2 out    [k=n*32+h][b]
__device__ __align__(16) float g_partial[SPLITS * Jj * Bz];
__device__ __align__(16) float g_hid[Jj * Bz];  // relu(flat@Wp1+bp1) [j][b]

// ----------------------------- helpers --------------------------------------
__device__ __forceinline__ unsigned long long ffma2(unsigned long long a,
                                                    unsigned long long b,
                                                    unsigned long long c) {
    unsigned long long d;
    asm("fma.rn.f32x2 %0, %1, %2, %3;" : "=l"(d) : "l"(a), "l"(b), "l"(c));
    return d;
}
__device__ __forceinline__ unsigned long long pack2(float x) {
    unsigned long long d;
    unsigned u = __float_as_uint(x);
    asm("mov.b64 %0, {%1, %1};" : "=l"(d) : "r"(u));
    return d;
}
__device__ __forceinline__ int load_idx(const void* ei, long long pos) {
    if (g_is64) return (int)((const long long*)ei)[pos];
    return ((const int*)ei)[pos];
}

// ------------------- 1. init: zero deg + detect int32/int64 -----------------
// blocks 0..19 zero g_deg, block 20 detects index dtype
__global__ void k_init(const void* ei) {
    int tid = threadIdx.x;
    if (blockIdx.x < 20) {
        int i = blockIdx.x * 256 + tid;
        if (i < Nn) g_deg[i] = 0;
        return;
    }
    const unsigned* w = (const unsigned*)ei;
    unsigned o = 0;
    for (int i = tid; i < 2048; i += 256) o |= w[2 * i + 1]; // high words if i64
    __shared__ unsigned red[256];
    red[tid] = o;
    __syncthreads();
    for (int s = 128; s > 0; s >>= 1) {
        if (tid < s) red[tid] |= red[tid + s];
        __syncthreads();
    }
    if (tid == 0) g_is64 = (red[0] == 0u) ? 1 : 0;
}

// ------------------- 2. degree histogram ------------------------------------
__global__ void k_degree(const void* ei) {
    int idx = blockIdx.x * 256 + threadIdx.x;
    if (idx >= NE) return;
    int d = (idx < Ee) ? load_idx(ei, (long long)Ee + idx) : (idx - Ee);
    atomicAdd(&g_deg[d], 1);
}

// ------------------- 3. scan: ptr, cursor, dinv (warp-shuffle) --------------
__global__ void __launch_bounds__(1024) k_scan() {
    __shared__ int warpsum[32];
    int t = threadIdx.x;
    int lane = t & 31, wid = t >> 5;
    int base = t * 5;
    int v[5];
    int s = 0;
#pragma unroll
    for (int i = 0; i < 5; i++) {
        int n = base + i;
        int d = (n < Nn) ? g_deg[n] : 0;
        v[i] = s;
        s += d;
        if (n < Nn) g_dinv[n] = rsqrtf((float)d);   // deg >= 1 (self loop)
    }
    int x = s;
#pragma unroll
    for (int o = 1; o < 32; o <<= 1) {
        int y = __shfl_up_sync(0xffffffffu, x, o);
        if (lane >= o) x += y;
    }
    if (lane == 31) warpsum[wid] = x;
    __syncthreads();
    if (wid == 0) {
        int y = warpsum[lane];
#pragma unroll
        for (int o = 1; o < 32; o <<= 1) {
            int z = __shfl_up_sync(0xffffffffu, y, o);
            if (lane >= o) y += z;
        }
        warpsum[lane] = y;
    }
    __syncthreads();
    int excl = x - s + ((wid > 0) ? warpsum[wid - 1] : 0);
#pragma unroll
    for (int i = 0; i < 5; i++) {
        int n = base + i;
        if (n < Nn) { g_ptr[n] = excl + v[i]; g_cursor[n] = excl + v[i]; }
    }
    if (t == 0) g_ptr[Nn] = NE;
}

// ------------------- 4. bucket edges + y1 = dinv*(X@W1), merged -------------
#define BUCKET_BLOCKS ((NE + 255) / 256)   // 645
#define XW1_BLOCKS (Bz * Nn / 32)          // 2500
__global__ void __launch_bounds__(256) k_bucket_xw1(const void* ei,
                                                    const float* __restrict__ X,
                                                    const float* __restrict__ W1) {
    int tid = threadIdx.x;
    if (blockIdx.x < BUCKET_BLOCKS) {
        int idx = blockIdx.x * 256 + tid;
        if (idx >= NE) return;
        int d, s;
        if (idx < Ee) {
            d = load_idx(ei, (long long)Ee + idx);
            s = load_idx(ei, idx);
        } else {
            d = s = idx - Ee;
        }
        int pos = atomicAdd(&g_cursor[d], 1);
        g_csr_src[pos] = s * Hh;   // pre-scaled offset within [b] slab
        return;
    }
    // ---- xw1 part ----
    __shared__ float sW[Ff * Hh];      // 8KB
    __shared__ float sX[Ff * 33];      // [f][row] padded
    int rbase = (blockIdx.x - BUCKET_BLOCKS) * 32;
    for (int i = tid; i < Ff * Hh; i += 256) sW[i] = W1[i];
    for (int i = tid; i < 32 * Ff; i += 256) {
        int row = i >> 6, f = i & 63;
        sX[f * 33 + row] = X[(size_t)(rbase + row) * Ff + f];
    }
    __syncthreads();
    int row = tid >> 3;
    int h0 = (tid & 7) * 4;
    int r = rbase + row;               // r = b*5000 + n
    float a0 = 0.f, a1 = 0.f, a2 = 0.f, a3 = 0.f;
#pragma unroll
    for (int f = 0; f < Ff; f++) {
        float x = sX[f * 33 + row];
        float4 w = *(const float4*)&sW[f * Hh + h0];
        a0 += x * w.x; a1 += x * w.y; a2 += x * w.z; a3 += x * w.w;
    }
    float di = g_dinv[r % Nn];
    float4 o = make_float4(di * a0, di * a1, di * a2, di * a3);
    *(float4*)&g_y1[(size_t)r * Hh + h0] = o;
}

// ------------------- 5. layer1 aggregate + relu + @W2 fused ------------------
// warp w = batch b; lanes = h. No block barriers in main loop.
__global__ void __launch_bounds__(512) k_agg1(const float* __restrict__ W2,
                                              const float* __restrict__ b1) {
    __shared__ float sW2[Hh * Hh];     // 4KB
    int d = blockIdx.x;
    int tid = threadIdx.x;
    int b = tid >> 5, h = tid & 31;
    sW2[tid] = W2[tid];
    sW2[tid + 512] = W2[tid + 512];
    __syncthreads();
    int start = __ldg(&g_ptr[d]), end = __ldg(&g_ptr[d + 1]);
    const float* yb = g_y1 + (size_t)b * NH + h;
    float a0 = 0.f, a1 = 0.f, a2 = 0.f, a3 = 0.f;
    int e = start;
    for (; e + 3 < end; e += 4) {
        int o0 = __ldg(&g_csr_src[e]);
        int o1 = __ldg(&g_csr_src[e + 1]);
        int o2 = __ldg(&g_csr_src[e + 2]);
        int o3 = __ldg(&g_csr_src[e + 3]);
        a0 += __ldg(yb + o0);
        a1 += __ldg(yb + o1);
        a2 += __ldg(yb + o2);
        a3 += __ldg(yb + o3);
    }
    for (; e < end; e++) a0 += __ldg(yb + __ldg(&g_csr_src[e]));
    float di = g_dinv[d];
    float hv = fmaxf(di * ((a0 + a1) + (a2 + a3)) + __ldg(&b1[h]), 0.f);
    // W2 multiply via warp shuffles (hv lives on lane h')
    float a = 0.f;
#pragma unroll
    for (int hp = 0; hp < Hh; hp++) {
        float v = __shfl_sync(0xffffffffu, hv, hp);
        a = fmaf(v, sW2[hp * Hh + h], a);
    }
    g_y2[(size_t)b * NH + (size_t)d * Hh + h] = di * a;
}

// ------------------- 6. layer2 aggregate + relu -> flatT ---------------------
__global__ void __launch_bounds__(512) k_agg2(const float* __restrict__ b2) {
    __shared__ float sT[32 * 17];
    int d = blockIdx.x;
    int tid = threadIdx.x;
    int b = tid >> 5, h = tid & 31;
    int start = __ldg(&g_ptr[d]), end = __ldg(&g_ptr[d + 1]);
    const float* yb = g_y2 + (size_t)b * NH + h;
    float a0 = 0.f, a1 = 0.f, a2 = 0.f, a3 = 0.f;
    int e = start;
    for (; e + 3 < end; e += 4) {
        int o0 = __ldg(&g_csr_src[e]);
        int o1 = __ldg(&g_csr_src[e + 1]);
        int o2 = __ldg(&g_csr_src[e + 2]);
        int o3 = __ldg(&g_csr_src[e + 3]);
        a0 += __ldg(yb + o0);
        a1 += __ldg(yb + o1);
        a2 += __ldg(yb + o2);
        a3 += __ldg(yb + o3);
    }
    for (; e < end; e++) a0 += __ldg(yb + __ldg(&g_csr_src[e]));
    float di = g_dinv[d];
    float v = fmaxf(di * ((a0 + a1) + (a2 + a3)) + __ldg(&b2[h]), 0.f);
    sT[h * 17 + b] = v;
    __syncthreads();
    g_flatT[(size_t)d * 512 + tid] = sT[(tid >> 4) * 17 + (tid & 15)];
}

// ------------------- 7. big GEMM: partial[split] = flatT^T chunk @ Wp1 -------
// Whole flatT k-slice staged in SMEM; Wp1 double-buffered in reg batches of 8.
__global__ void __launch_bounds__(256) k_gemm1(const float* __restrict__ Wp1) {
    __shared__ __align__(16) unsigned long long sF[KLEN * 8];  // 34816 B
    int t = threadIdx.x, sp = blockIdx.x;
    int ks = sp * KLEN;
    int klen = NH - ks;
    if (klen > KLEN) klen = KLEN;
    if (klen < 0) klen = 0;
    // stage flatT slice (klen*16 floats = klen*4 ulonglong2)
    const ulonglong2* fp = (const ulonglong2*)(g_flatT + (size_t)ks * 16);
    ulonglong2* sF2 = (ulonglong2*)sF;
    for (int i = t; i < klen * 4; i += 256) sF2[i] = __ldg(&fp[i]);
    __syncthreads();

    const float2* wp = (const float2*)Wp1 + (size_t)ks * 256 + t;
    unsigned long long acc0[8], acc1[8];
#pragma unroll
    for (int p = 0; p < 8; p++) { acc0[p] = 0ull; acc1[p] = 0ull; }

    int nb = klen >> 3;                // batches of 8 k-rows (klen always mult of 8)
    if (nb > 0) {
        float2 wbuf[8];
#pragma unroll
        for (int i = 0; i < 8; i++) wbuf[i] = __ldg(wp + i * 256);
        for (int bi = 0; bi < nb; bi++) {
            float2 wnext[8];
            if (bi + 1 < nb) {
                const float2* wq = wp + (size_t)(bi + 1) * 8 * 256;
#pragma unroll
                for (int i = 0; i < 8; i++) wnext[i] = __ldg(wq + i * 256);
            }
#pragma unroll
            for (int i = 0; i < 8; i++) {
                int kl = bi * 8 + i;
                unsigned long long wa = pack2(wbuf[i].x);
                unsigned long long wb = pack2(wbuf[i].y);
                const ulonglong2* f2 = (const ulonglong2*)&sF[kl * 8];
#pragma unroll
                for (int q = 0; q < 4; q++) {
                    ulonglong2 fv = f2[q];
                    acc0[2 * q]     = ffma2(fv.x, wa, acc0[2 * q]);
                    acc0[2 * q + 1] = ffma2(fv.y, wa, acc0[2 * q + 1]);
                    acc1[2 * q]     = ffma2(fv.x, wb, acc1[2 * q]);
                    acc1[2 * q + 1] = ffma2(fv.y, wb, acc1[2 * q + 1]);
                }
            }
#pragma unroll
            for (int i = 0; i < 8; i++) wbuf[i] = wnext[i];
        }
    }
    // store partials: layout [sp][j][b] with j0 = 2t
    unsigned long long* po = (unsigned long long*)g_partial;
    size_t base = (size_t)sp * 4096 + (size_t)(2 * t) * 8;
#pragma unroll
    for (int p = 0; p < 8; p++) {
        po[base + p] = acc0[p];
        po[base + 8 + p] = acc1[p];
    }
}

// ------------------- 8. reduce partials + bias + relu ------------------------
__global__ void __launch_bounds__(256) k_reduce(const float* __restrict__ bp1) {
    int idx = blockIdx.x * 256 + threadIdx.x;   // [j][b], 8192 total
    float s = 0.f;
#pragma unroll 8
    for (int sp = 0; sp < SPLITS; sp++) s += g_partial[(size_t)sp * 8192 + idx];
    g_hid[idx] = fmaxf(s + __ldg(&bp1[idx >> 4]), 0.f);
}

// ------------------- 9. final tiny GEMM ------------------------------------
__global__ void __launch_bounds__(256) k_out(const float* __restrict__ Wp2,
                                             const float* __restrict__ bp2,
                                             float* __restrict__ out) {
    int tid = threadIdx.x;
    int b = tid >> 4, a = tid & 15;
    float acc = 0.f;
#pragma unroll 4
    for (int j = 0; j < Jj; j++)
        acc += g_hid[j * 16 + b] * __ldg(&Wp2[j * 16 + a]);
    out[tid] = acc + __ldg(&bp2[a]);
}

// ----------------------------- launcher -------------------------------------
extern "C" void kernel_launch(void* const* d_in, const int* in_sizes, int n_in,
                              void* d_out, int out_size) {
    const float* features = (const float*)d_in[0];
    const void*  edge_ix  = d_in[1];
    const float* W1  = (const float*)d_in[2];
    const float* b1  = (const float*)d_in[3];
    const float* W2  = (const float*)d_in[4];
    const float* b2  = (const float*)d_in[5];
    const float* Wp1 = (const float*)d_in[6];
    const float* bp1 = (const float*)d_in[7];
    const float* Wp2 = (const float*)d_in[8];
    const float* bp2 = (const float*)d_in[9];
    float* out = (float*)d_out;

    k_init<<<21, 256>>>(edge_ix);
    k_degree<<<(NE + 255) / 256, 256>>>(edge_ix);
    k_scan<<<1, 1024>>>();
    k_bucket_xw1<<<BUCKET_BLOCKS + XW1_BLOCKS, 256>>>(edge_ix, features, W1);
    k_agg1<<<Nn, 512>>>(W2, b1);
    k_agg2<<<Nn, 512>>>(b2);
    k_gemm1<<<SPLITS, 256>>>(Wp1);
    k_reduce<<<Jj * Bz / 256, 256>>>(bp1);
    k_out<<<1, 256>>>(Wp2, bp2, out);
}